// round 14
// baseline (speedup 1.0000x reference)
#include <cuda_runtime.h>
#include <cuda_bf16.h>
#include <cstdint>

#define NN 50000
#define NE 640000
#define DD 128
#define NCLS 64
#define NB 49          // scan blocks: 49*1024 = 50176 >= NN

// ---------------- scratch (device globals) ----------------
__device__ uint4  g_Ah[(size_t)NN * 16];   // [NN][128] bf16 hi
__device__ uint4  g_Al[(size_t)NN * 16];   // [NN][128] bf16 lo
__device__ float4 g_bufB[(size_t)NN * 32]; // [NN][128] f32 (h1 pre-scaled by dinv)
__device__ uint4  g_W1h[128 * 16], g_W1l[128 * 16];  // W^T [n][k] bf16
__device__ uint4  g_W2h[128 * 16], g_W2l[128 * 16];
__device__ uint4  g_W3h[64 * 16],  g_W3l[64 * 16];
__device__ int4   g_cnt4[NB * 256];        // 50176 counters
__device__ int    g_bsum[NB];
__device__ int    g_bscan[NB];
__device__ int    g_off[NN + 1];
__device__ int    g_cur[NN];
__device__ float  g_dinv[NN];
__device__ int    g_col[NE];
__device__ int4   g_src4[NE / 4];
__device__ int4   g_dst4[NE / 4];

// ---------------- helpers ----------------
__device__ __forceinline__ uint32_t smem_u32(const void* p) {
    uint32_t a;
    asm("{ .reg .u64 t; cvta.to.shared.u64 t, %1; cvt.u32.u64 %0, t; }" : "=r"(a) : "l"(p));
    return a;
}
__device__ __forceinline__ void ldsm_x4(uint32_t& r0, uint32_t& r1, uint32_t& r2, uint32_t& r3,
                                        uint32_t addr) {
    asm volatile("ldmatrix.sync.aligned.m8n8.x4.shared.b16 {%0,%1,%2,%3}, [%4];"
                 : "=r"(r0), "=r"(r1), "=r"(r2), "=r"(r3) : "r"(addr));
}
__device__ __forceinline__ void mma_bf16(float* c, uint32_t a0, uint32_t a1, uint32_t a2,
                                         uint32_t a3, uint32_t b0, uint32_t b1) {
    asm volatile(
        "mma.sync.aligned.m16n8k16.row.col.f32.bf16.bf16.f32 "
        "{%0,%1,%2,%3}, {%4,%5,%6,%7}, {%8,%9}, {%0,%1,%2,%3};"
        : "+f"(c[0]), "+f"(c[1]), "+f"(c[2]), "+f"(c[3])
        : "r"(a0), "r"(a1), "r"(a2), "r"(a3), "r"(b0), "r"(b1));
}
__device__ __forceinline__ int warp_iscan(int v, int lane) {
    #pragma unroll
    for (int d = 1; d < 32; d <<= 1) {
        int t = __shfl_up_sync(0xffffffffu, v, d);
        if (lane >= d) v += t;
    }
    return v;
}

// ---------------- CSR build ----------------
__global__ void zero_cnt_kernel() {
    int i = blockIdx.x * blockDim.x + threadIdx.x;
    if (i < NB * 256) g_cnt4[i] = make_int4(0, 0, 0, 0);
}

// fused dtype-detect + normalize + histogram, 4 edges/thread (verified R12)
__global__ void edges_kernel(const unsigned int* __restrict__ raw) {
    __shared__ int s_is64;
    if (threadIdx.x < 32) {
        size_t k = (size_t)threadIdx.x * (NE / 32);
        unsigned int hi = raw[2 * k + 1];
        unsigned int any = __ballot_sync(0xffffffffu, hi != 0u);
        if (threadIdx.x == 0) s_is64 = (any == 0u);
    }
    __syncthreads();
    int is64 = s_is64;
    int t = blockIdx.x * blockDim.x + threadIdx.x;
    if (t >= NE / 4) return;
    const uint4* raw4 = (const uint4*)raw;
    int4 s, d;
    if (is64) {
        uint4 a = raw4[2 * (size_t)t],            b = raw4[2 * (size_t)t + 1];
        uint4 c = raw4[(size_t)NE / 2 + 2 * t],   e = raw4[(size_t)NE / 2 + 2 * t + 1];
        s = make_int4((int)a.x, (int)a.z, (int)b.x, (int)b.z);
        d = make_int4((int)c.x, (int)c.z, (int)e.x, (int)e.z);
    } else {
        uint4 a = raw4[t], c = raw4[NE / 4 + t];
        s = make_int4((int)a.x, (int)a.y, (int)a.z, (int)a.w);
        d = make_int4((int)c.x, (int)c.y, (int)c.z, (int)c.w);
    }
    s.x = min(max(s.x, 0), NN - 1); s.y = min(max(s.y, 0), NN - 1);
    s.z = min(max(s.z, 0), NN - 1); s.w = min(max(s.w, 0), NN - 1);
    d.x = min(max(d.x, 0), NN - 1); d.y = min(max(d.y, 0), NN - 1);
    d.z = min(max(d.z, 0), NN - 1); d.w = min(max(d.w, 0), NN - 1);
    g_src4[t] = s;
    g_dst4[t] = d;
    int* cnt = (int*)g_cnt4;
    atomicAdd(&cnt[d.x], 1); atomicAdd(&cnt[d.y], 1);
    atomicAdd(&cnt[d.z], 1); atomicAdd(&cnt[d.w], 1);
}

// ---- multi-block scan (verified R10) ----
__global__ void scan1_kernel() {
    __shared__ int wsum[8];
    int t = threadIdx.x, b = blockIdx.x;
    int lane = t & 31, w = t >> 5;
    int4 v = g_cnt4[b * 256 + t];
    int s = v.x + v.y + v.z + v.w;
    int inc = warp_iscan(s, lane);
    if (lane == 31) wsum[w] = inc;
    __syncthreads();
    if (t == 0) {
        int tot = 0;
        #pragma unroll
        for (int i = 0; i < 8; ++i) tot += wsum[i];
        g_bsum[b] = tot;
    }
}

__global__ void scan2_kernel() {
    __shared__ int w0tot;
    int t = threadIdx.x, lane = t & 31, w = t >> 5;
    int s = (t < NB) ? g_bsum[t] : 0;
    int inc = warp_iscan(s, lane);
    if (w == 0 && lane == 31) w0tot = inc;
    __syncthreads();
    int excl = inc - s + (w ? w0tot : 0);
    if (t < NB) g_bscan[t] = excl;
    if (t == NB - 1) g_off[NN] = excl + s;
}

__global__ void scan3_kernel() {
    __shared__ int wsum[8];
    int t = threadIdx.x, b = blockIdx.x;
    int lane = t & 31, w = t >> 5;
    int4 v = g_cnt4[b * 256 + t];
    int s = v.x + v.y + v.z + v.w;
    int inc = warp_iscan(s, lane);
    if (lane == 31) wsum[w] = inc;
    __syncthreads();
    int woff = 0;
    #pragma unroll
    for (int i = 0; i < 8; ++i) if (i < w) woff += wsum[i];
    int excl = g_bscan[b] + woff + inc - s;
    int i0 = (b * 256 + t) * 4;
    int e0 = excl, e1 = e0 + v.x, e2 = e1 + v.y, e3 = e2 + v.z;
    if (i0 + 0 < NN) { g_off[i0 + 0] = e0; g_cur[i0 + 0] = e0; g_dinv[i0 + 0] = rsqrtf((float)(v.x + 1)); }
    if (i0 + 1 < NN) { g_off[i0 + 1] = e1; g_cur[i0 + 1] = e1; g_dinv[i0 + 1] = rsqrtf((float)(v.y + 1)); }
    if (i0 + 2 < NN) { g_off[i0 + 2] = e2; g_cur[i0 + 2] = e2; g_dinv[i0 + 2] = rsqrtf((float)(v.z + 1)); }
    if (i0 + 3 < NN) { g_off[i0 + 3] = e3; g_cur[i0 + 3] = e3; g_dinv[i0 + 3] = rsqrtf((float)(v.w + 1)); }
}

// 4 edges/thread (verified R12)
__global__ void fill_kernel() {
    int t = blockIdx.x * blockDim.x + threadIdx.x;
    if (t >= NE / 4) return;
    int4 s = g_src4[t], d = g_dst4[t];
    int p;
    p = atomicAdd(&g_cur[d.x], 1); g_col[p] = s.x;
    p = atomicAdd(&g_cur[d.y], 1); g_col[p] = s.y;
    p = atomicAdd(&g_cur[d.z], 1); g_col[p] = s.z;
    p = atomicAdd(&g_cur[d.w], 1); g_col[p] = s.w;
}

// ---------------- weight split ----------------
__global__ void split_w_kernel(const float* __restrict__ W1, const float* __restrict__ W2,
                               const float* __restrict__ W3) {
    int i = blockIdx.x * blockDim.x + threadIdx.x;
    float v; __nv_bfloat16* dh; __nv_bfloat16* dl; int n, k;
    if (i < 16384) {
        v = W1[i]; k = i >> 7; n = i & 127;
        dh = (__nv_bfloat16*)g_W1h; dl = (__nv_bfloat16*)g_W1l;
    } else if (i < 32768) {
        int j = i - 16384;
        v = W2[j]; k = j >> 7; n = j & 127;
        dh = (__nv_bfloat16*)g_W2h; dl = (__nv_bfloat16*)g_W2l;
    } else if (i < 40960) {
        int j = i - 32768;
        v = W3[j]; k = j >> 6; n = j & 63;
        dh = (__nv_bfloat16*)g_W3h; dl = (__nv_bfloat16*)g_W3l;
    } else return;
    __nv_bfloat16 h = __float2bfloat16(v);
    __nv_bfloat16 l = __float2bfloat16(v - __bfloat162float(h));
    dh[n * 128 + k] = h;
    dl[n * 128 + k] = l;
}

// ---------------- sparse propagate -> bf16 hi/lo split (R10 core) ----------------
// FROM_X: read external x (needs per-edge dinv). Else read g_bufB which is
// PRE-SCALED by dinv: out[i] = di*( sum_e hs[src] + hs[i] ).
template<bool FROM_X>
__global__ void prop_kernel(const float* __restrict__ xin) {
    int warp = (blockIdx.x * blockDim.x + threadIdx.x) >> 5;
    int lane = threadIdx.x & 31;
    if (warp >= NN) return;
    const float4* X4 = FROM_X ? (const float4*)xin : (const float4*)g_bufB;
    int i = warp;
    float di = g_dinv[i];
    float4 v = X4[(size_t)i * 32 + lane];
    float ax, ay, az, aw;
    if (FROM_X) { ax = di * v.x; ay = di * v.y; az = di * v.z; aw = di * v.w; }
    else        { ax = v.x;      ay = v.y;      az = v.z;      aw = v.w; }
    int e  = g_off[i];
    int e1 = g_off[i + 1];
    for (; e + 4 <= e1; e += 4) {
        int s0 = g_col[e + 0], s1 = g_col[e + 1], s2 = g_col[e + 2], s3 = g_col[e + 3];
        float4 v0 = X4[(size_t)s0 * 32 + lane];
        float4 v1 = X4[(size_t)s1 * 32 + lane];
        float4 v2 = X4[(size_t)s2 * 32 + lane];
        float4 v3 = X4[(size_t)s3 * 32 + lane];
        if (FROM_X) {
            float w0 = g_dinv[s0], w1 = g_dinv[s1], w2 = g_dinv[s2], w3 = g_dinv[s3];
            ax += w0 * v0.x + w1 * v1.x + w2 * v2.x + w3 * v3.x;
            ay += w0 * v0.y + w1 * v1.y + w2 * v2.y + w3 * v3.y;
            az += w0 * v0.z + w1 * v1.z + w2 * v2.z + w3 * v3.z;
            aw += w0 * v0.w + w1 * v1.w + w2 * v2.w + w3 * v3.w;
        } else {
            ax += v0.x + v1.x + v2.x + v3.x;
            ay += v0.y + v1.y + v2.y + v3.y;
            az += v0.z + v1.z + v2.z + v3.z;
            aw += v0.w + v1.w + v2.w + v3.w;
        }
    }
    for (; e < e1; ++e) {
        int s = g_col[e];
        float4 vv = X4[(size_t)s * 32 + lane];
        if (FROM_X) {
            float w = g_dinv[s];
            ax += w * vv.x; ay += w * vv.y; az += w * vv.z; aw += w * vv.w;
        } else {
            ax += vv.x; ay += vv.y; az += vv.z; aw += vv.w;
        }
    }
    ax *= di; ay *= di; az *= di; aw *= di;
    __nv_bfloat16 hx = __float2bfloat16(ax), hy = __float2bfloat16(ay);
    __nv_bfloat16 hz = __float2bfloat16(az), hw = __float2bfloat16(aw);
    __nv_bfloat16 lx = __float2bfloat16(ax - __bfloat162float(hx));
    __nv_bfloat16 ly = __float2bfloat16(ay - __bfloat162float(hy));
    __nv_bfloat16 lz = __float2bfloat16(az - __bfloat162float(hz));
    __nv_bfloat16 lw = __float2bfloat16(aw - __bfloat162float(hw));
    uint2 hv, lv;
    hv.x = ((uint32_t)__bfloat16_as_ushort(hy) << 16) | __bfloat16_as_ushort(hx);
    hv.y = ((uint32_t)__bfloat16_as_ushort(hw) << 16) | __bfloat16_as_ushort(hz);
    lv.x = ((uint32_t)__bfloat16_as_ushort(ly) << 16) | __bfloat16_as_ushort(lx);
    lv.y = ((uint32_t)__bfloat16_as_ushort(lw) << 16) | __bfloat16_as_ushort(lz);
    ((uint2*)g_Ah)[(size_t)i * 32 + lane] = hv;
    ((uint2*)g_Al)[(size_t)i * 32 + lane] = lv;
}

// ---------------- HMMA bf16 3-term GEMM (verified R8/R10) ----------------
// OUT: 0 = f32 g_bufB PRE-SCALED by dinv[row] (feeds layer-2 prop),
//      1 = bf16 split g_Ah/g_Al, 2 = f32 outp.
template<int N, bool RELU, int OUT, int LAY>
__global__ void __launch_bounds__(256) mma_gemm(const float* __restrict__ bias,
                                                float* __restrict__ outp) {
    constexpr int NT = N / 8;
    __shared__ uint4 sAh[128 * 4], sAl[128 * 4];
    __shared__ uint4 sBh[N * 4],   sBl[N * 4];

    const uint4* Wh = (LAY == 1) ? g_W1h : (LAY == 2) ? g_W2h : g_W3h;
    const uint4* Wl = (LAY == 1) ? g_W1l : (LAY == 2) ? g_W2l : g_W3l;

    int tid = threadIdx.x;
    int wid = tid >> 5;
    int lid = tid & 31;
    int m0  = blockIdx.x * 128;

    float acc[NT][4];
    #pragma unroll
    for (int t = 0; t < NT; ++t)
        #pragma unroll
        for (int j = 0; j < 4; ++j) acc[t][j] = 0.f;

    uint32_t sAh_b = smem_u32(sAh), sAl_b = smem_u32(sAl);
    uint32_t sBh_b = smem_u32(sBh), sBl_b = smem_u32(sBl);

    uint32_t a_row  = lid & 15;
    uint32_t a_half = lid >> 4;
    uint32_t a_x    = (a_row >> 1) & 3;
    uint32_t a_base = (wid * 16 + a_row) * 64;
    uint32_t b_c    = (lid & 7) + ((lid >> 4) & 1) * 8;
    uint32_t b_half = (lid >> 3) & 1;
    uint32_t b_x    = (b_c >> 1) & 3;
    uint32_t b_base = b_c * 64;

    for (int c = 0; c < 4; ++c) {
        #pragma unroll
        for (int f = tid; f < 128 * 4; f += 256) {
            int row = f >> 2, ch = f & 3;
            int gr = m0 + row;
            uint4 vh = make_uint4(0, 0, 0, 0), vl = vh;
            if (gr < NN) {
                size_t gi = (size_t)gr * 16 + c * 4 + ch;
                vh = g_Ah[gi]; vl = g_Al[gi];
            }
            int du = row * 4 + (ch ^ ((row >> 1) & 3));
            sAh[du] = vh; sAl[du] = vl;
        }
        #pragma unroll
        for (int f = tid; f < N * 4; f += 256) {
            int row = f >> 2, ch = f & 3;
            size_t gi = (size_t)row * 16 + c * 4 + ch;
            int du = row * 4 + (ch ^ ((row >> 1) & 3));
            sBh[du] = Wh[gi]; sBl[du] = Wl[gi];
        }
        __syncthreads();

        #pragma unroll
        for (int ks = 0; ks < 2; ++ks) {
            uint32_t aoff = a_base + (((ks * 2 + a_half) ^ a_x) << 4);
            uint32_t ah0, ah1, ah2, ah3, al0, al1, al2, al3;
            ldsm_x4(ah0, ah1, ah2, ah3, sAh_b + aoff);
            ldsm_x4(al0, al1, al2, al3, sAl_b + aoff);
            #pragma unroll
            for (int jp = 0; jp < NT / 2; ++jp) {
                uint32_t boff = jp * 1024 + b_base + (((ks * 2 + b_half) ^ b_x) << 4);
                uint32_t bh0, bh1, bh2, bh3, bl0, bl1, bl2, bl3;
                ldsm_x4(bh0, bh1, bh2, bh3, sBh_b + boff);
                mma_bf16(acc[2 * jp],     ah0, ah1, ah2, ah3, bh0, bh1);
                mma_bf16(acc[2 * jp + 1], ah0, ah1, ah2, ah3, bh2, bh3);
                mma_bf16(acc[2 * jp],     al0, al1, al2, al3, bh0, bh1);
                mma_bf16(acc[2 * jp + 1], al0, al1, al2, al3, bh2, bh3);
                ldsm_x4(bl0, bl1, bl2, bl3, sBl_b + boff);
                mma_bf16(acc[2 * jp],     ah0, ah1, ah2, ah3, bl0, bl1);
                mma_bf16(acc[2 * jp + 1], ah0, ah1, ah2, ah3, bl2, bl3);
            }
        }
        __syncthreads();
    }

    int g = lid >> 2, q = lid & 3;
    int r0 = m0 + wid * 16 + g;
    int r1 = r0 + 8;
    float sd0 = 1.f, sd1 = 1.f;
    if (OUT == 0) {
        sd0 = (r0 < NN) ? g_dinv[r0] : 0.f;
        sd1 = (r1 < NN) ? g_dinv[r1] : 0.f;
    }
    #pragma unroll
    for (int nt = 0; nt < NT; ++nt) {
        int col = nt * 8 + 2 * q;
        float2 bb = *(const float2*)&bias[col];
        float v0 = acc[nt][0] + bb.x, v1 = acc[nt][1] + bb.y;
        float v2 = acc[nt][2] + bb.x, v3 = acc[nt][3] + bb.y;
        if (RELU) {
            v0 = fmaxf(v0, 0.f); v1 = fmaxf(v1, 0.f);
            v2 = fmaxf(v2, 0.f); v3 = fmaxf(v3, 0.f);
        }
        if (OUT == 1) {
            __nv_bfloat16 h0 = __float2bfloat16(v0), h1 = __float2bfloat16(v1);
            __nv_bfloat16 h2 = __float2bfloat16(v2), h3 = __float2bfloat16(v3);
            ushort2 hp0, hp1, lp0, lp1;
            hp0.x = __bfloat16_as_ushort(h0); hp0.y = __bfloat16_as_ushort(h1);
            hp1.x = __bfloat16_as_ushort(h2); hp1.y = __bfloat16_as_ushort(h3);
            lp0.x = __bfloat16_as_ushort(__float2bfloat16(v0 - __bfloat162float(h0)));
            lp0.y = __bfloat16_as_ushort(__float2bfloat16(v1 - __bfloat162float(h1)));
            lp1.x = __bfloat16_as_ushort(__float2bfloat16(v2 - __bfloat162float(h2)));
            lp1.y = __bfloat16_as_ushort(__float2bfloat16(v3 - __bfloat162float(h3)));
            if (r0 < NN) {
                *(ushort2*)((__nv_bfloat16*)g_Ah + (size_t)r0 * 128 + col) = hp0;
                *(ushort2*)((__nv_bfloat16*)g_Al + (size_t)r0 * 128 + col) = lp0;
            }
            if (r1 < NN) {
                *(ushort2*)((__nv_bfloat16*)g_Ah + (size_t)r1 * 128 + col) = hp1;
                *(ushort2*)((__nv_bfloat16*)g_Al + (size_t)r1 * 128 + col) = lp1;
            }
        } else {
            float* C = (OUT == 2) ? outp : (float*)g_bufB;
            if (r0 < NN) *(float2*)&C[(size_t)r0 * N + col] = make_float2(v0 * sd0, v1 * sd0);
            if (r1 < NN) *(float2*)&C[(size_t)r1 * N + col] = make_float2(v2 * sd1, v3 * sd1);
        }
    }
}

// ---------------- launch ----------------
extern "C" void kernel_launch(void* const* d_in, const int* in_sizes, int n_in,
                              void* d_out, int out_size) {
    const float* x  = (const float*)d_in[0];
    const float* W1 = (const float*)d_in[2];
    const float* b1 = (const float*)d_in[3];
    const float* W2 = (const float*)d_in[4];
    const float* b2 = (const float*)d_in[5];
    const float* Wl = (const float*)d_in[6];
    const float* bl = (const float*)d_in[7];
    float*       out = (float*)d_out;

    // CSR build + weight split
    zero_cnt_kernel<<<NB, 256>>>();
    edges_kernel<<<(NE / 4 + 255) / 256, 256>>>((const unsigned int*)d_in[1]);
    split_w_kernel<<<160, 256>>>(W1, W2, Wl);
    scan1_kernel<<<NB, 256>>>();
    scan2_kernel<<<1, 64>>>();
    scan3_kernel<<<NB, 256>>>();
    fill_kernel<<<(NE / 4 + 255) / 256, 256>>>();

    dim3 pgrid((NN + 7) / 8);
    dim3 ggrid((NN + 127) / 128);   // 391 CTAs

    // layer 1: propagate(x) -> Ah/Al ; GEMM -> bufB (f32, relu, PRE-SCALED by dinv)
    prop_kernel<true><<<pgrid, 256>>>(x);
    mma_gemm<128, true, 0, 1><<<ggrid, 256>>>(b1, nullptr);
    // layer 2: propagate(bufB scaled) -> Ah/Al ; GEMM -> Ah/Al (bf16 split, relu)
    prop_kernel<false><<<pgrid, 256>>>(nullptr);
    mma_gemm<128, true, 1, 2><<<ggrid, 256>>>(b2, nullptr);
    // head: Ah/Al @ Wl + bl -> out
    mma_gemm<64, false, 2, 3><<<ggrid, 256>>>(bl, out);
}

// round 15
// speedup vs baseline: 1.4481x; 1.4481x over previous
#include <cuda_runtime.h>
#include <cuda_bf16.h>
#include <cstdint>

#define NN 50000
#define NE 640000
#define DD 128
#define NCLS 64
#define NB 49          // scan blocks: 49*1024 = 50176 >= NN

// ---------------- scratch (device globals) ----------------
__device__ uint4  g_Ah[(size_t)NN * 16];   // [NN][128] bf16 hi
__device__ uint4  g_Al[(size_t)NN * 16];   // [NN][128] bf16 lo
__device__ float4 g_bufB[(size_t)NN * 32]; // [NN][128] f32 (h1 pre-scaled by dinv)
__device__ uint4  g_W1h[128 * 16], g_W1l[128 * 16];  // W^T [n][k] bf16
__device__ uint4  g_W2h[128 * 16], g_W2l[128 * 16];
__device__ uint4  g_W3h[64 * 16],  g_W3l[64 * 16];
__device__ int4   g_cnt4[NB * 256];        // 50176 counters (16B-aligned)
__device__ int    g_bsum[NB];
__device__ int    g_bscan[NB];
__device__ int    g_off[NN + 1];
__device__ int    g_cur[NN];
__device__ float  g_dinv[NN];
__device__ int    g_col[NE];
__device__ int    g_src[NE];
__device__ int    g_dst[NE];

// ---------------- helpers ----------------
__device__ __forceinline__ uint32_t smem_u32(const void* p) {
    uint32_t a;
    asm("{ .reg .u64 t; cvta.to.shared.u64 t, %1; cvt.u32.u64 %0, t; }" : "=r"(a) : "l"(p));
    return a;
}
__device__ __forceinline__ void ldsm_x4(uint32_t& r0, uint32_t& r1, uint32_t& r2, uint32_t& r3,
                                        uint32_t addr) {
    asm volatile("ldmatrix.sync.aligned.m8n8.x4.shared.b16 {%0,%1,%2,%3}, [%4];"
                 : "=r"(r0), "=r"(r1), "=r"(r2), "=r"(r3) : "r"(addr));
}
__device__ __forceinline__ void mma_bf16(float* c, uint32_t a0, uint32_t a1, uint32_t a2,
                                         uint32_t a3, uint32_t b0, uint32_t b1) {
    asm volatile(
        "mma.sync.aligned.m16n8k16.row.col.f32.bf16.bf16.f32 "
        "{%0,%1,%2,%3}, {%4,%5,%6,%7}, {%8,%9}, {%0,%1,%2,%3};"
        : "+f"(c[0]), "+f"(c[1]), "+f"(c[2]), "+f"(c[3])
        : "r"(a0), "r"(a1), "r"(a2), "r"(a3), "r"(b0), "r"(b1));
}
__device__ __forceinline__ int warp_iscan(int v, int lane) {
    #pragma unroll
    for (int d = 1; d < 32; d <<= 1) {
        int t = __shfl_up_sync(0xffffffffu, v, d);
        if (lane >= d) v += t;
    }
    return v;
}

// ---------------- CSR build (R10 scalar forms — best latency hiding) ----------------
__global__ void zero_cnt_kernel() {
    int i = blockIdx.x * blockDim.x + threadIdx.x;
    if (i < NB * 256) g_cnt4[i] = make_int4(0, 0, 0, 0);
}

// fused dtype-detect + normalize + histogram, 1 edge/thread (verified R10)
__global__ void edges_kernel(const unsigned int* __restrict__ raw) {
    __shared__ int s_is64;
    if (threadIdx.x < 32) {
        size_t k = (size_t)threadIdx.x * (NE / 32);
        unsigned int hi = raw[2 * k + 1];
        unsigned int any = __ballot_sync(0xffffffffu, hi != 0u);
        if (threadIdx.x == 0) s_is64 = (any == 0u);
    }
    __syncthreads();
    int is64 = s_is64;
    int e = blockIdx.x * blockDim.x + threadIdx.x;
    if (e >= NE) return;
    const int* raw32 = (const int*)raw;
    int s, d;
    if (is64) { s = raw32[2 * (size_t)e]; d = raw32[2 * ((size_t)NE + e)]; }
    else      { s = raw32[e];             d = raw32[NE + e]; }
    s = min(max(s, 0), NN - 1);
    d = min(max(d, 0), NN - 1);
    g_src[e] = s;
    g_dst[e] = d;
    atomicAdd(&((int*)g_cnt4)[d], 1);
}

// ---- multi-block scan (verified R10) ----
__global__ void scan1_kernel() {
    __shared__ int wsum[8];
    int t = threadIdx.x, b = blockIdx.x;
    int lane = t & 31, w = t >> 5;
    int4 v = g_cnt4[b * 256 + t];
    int s = v.x + v.y + v.z + v.w;
    int inc = warp_iscan(s, lane);
    if (lane == 31) wsum[w] = inc;
    __syncthreads();
    if (t == 0) {
        int tot = 0;
        #pragma unroll
        for (int i = 0; i < 8; ++i) tot += wsum[i];
        g_bsum[b] = tot;
    }
}

__global__ void scan2_kernel() {
    __shared__ int w0tot;
    int t = threadIdx.x, lane = t & 31, w = t >> 5;
    int s = (t < NB) ? g_bsum[t] : 0;
    int inc = warp_iscan(s, lane);
    if (w == 0 && lane == 31) w0tot = inc;
    __syncthreads();
    int excl = inc - s + (w ? w0tot : 0);
    if (t < NB) g_bscan[t] = excl;
    if (t == NB - 1) g_off[NN] = excl + s;
}

__global__ void scan3_kernel() {
    __shared__ int wsum[8];
    int t = threadIdx.x, b = blockIdx.x;
    int lane = t & 31, w = t >> 5;
    int4 v = g_cnt4[b * 256 + t];
    int s = v.x + v.y + v.z + v.w;
    int inc = warp_iscan(s, lane);
    if (lane == 31) wsum[w] = inc;
    __syncthreads();
    int woff = 0;
    #pragma unroll
    for (int i = 0; i < 8; ++i) if (i < w) woff += wsum[i];
    int excl = g_bscan[b] + woff + inc - s;
    int i0 = (b * 256 + t) * 4;
    int e0 = excl, e1 = e0 + v.x, e2 = e1 + v.y, e3 = e2 + v.z;
    if (i0 + 0 < NN) { g_off[i0 + 0] = e0; g_cur[i0 + 0] = e0; g_dinv[i0 + 0] = rsqrtf((float)(v.x + 1)); }
    if (i0 + 1 < NN) { g_off[i0 + 1] = e1; g_cur[i0 + 1] = e1; g_dinv[i0 + 1] = rsqrtf((float)(v.y + 1)); }
    if (i0 + 2 < NN) { g_off[i0 + 2] = e2; g_cur[i0 + 2] = e2; g_dinv[i0 + 2] = rsqrtf((float)(v.z + 1)); }
    if (i0 + 3 < NN) { g_off[i0 + 3] = e3; g_cur[i0 + 3] = e3; g_dinv[i0 + 3] = rsqrtf((float)(v.w + 1)); }
}

// 1 edge/thread (verified R10)
__global__ void fill_kernel() {
    int e = blockIdx.x * blockDim.x + threadIdx.x;
    if (e < NE) {
        int p = atomicAdd(&g_cur[g_dst[e]], 1);
        g_col[p] = g_src[e];
    }
}

// ---------------- weight split ----------------
__global__ void split_w_kernel(const float* __restrict__ W1, const float* __restrict__ W2,
                               const float* __restrict__ W3) {
    int i = blockIdx.x * blockDim.x + threadIdx.x;
    float v; __nv_bfloat16* dh; __nv_bfloat16* dl; int n, k;
    if (i < 16384) {
        v = W1[i]; k = i >> 7; n = i & 127;
        dh = (__nv_bfloat16*)g_W1h; dl = (__nv_bfloat16*)g_W1l;
    } else if (i < 32768) {
        int j = i - 16384;
        v = W2[j]; k = j >> 7; n = j & 127;
        dh = (__nv_bfloat16*)g_W2h; dl = (__nv_bfloat16*)g_W2l;
    } else if (i < 40960) {
        int j = i - 32768;
        v = W3[j]; k = j >> 6; n = j & 63;
        dh = (__nv_bfloat16*)g_W3h; dl = (__nv_bfloat16*)g_W3l;
    } else return;
    __nv_bfloat16 h = __float2bfloat16(v);
    __nv_bfloat16 l = __float2bfloat16(v - __bfloat162float(h));
    dh[n * 128 + k] = h;
    dl[n * 128 + k] = l;
}

// ---------------- sparse propagate -> bf16 hi/lo split (R10 core + prefold) ----------------
// FROM_X: read external x (needs per-edge dinv). Else read g_bufB which is
// PRE-SCALED by dinv: out[i] = di*( sum_e hs[src] + hs[i] ).
template<bool FROM_X>
__global__ void prop_kernel(const float* __restrict__ xin) {
    int warp = (blockIdx.x * blockDim.x + threadIdx.x) >> 5;
    int lane = threadIdx.x & 31;
    if (warp >= NN) return;
    const float4* X4 = FROM_X ? (const float4*)xin : (const float4*)g_bufB;
    int i = warp;
    float di = g_dinv[i];
    float4 v = X4[(size_t)i * 32 + lane];
    float ax, ay, az, aw;
    if (FROM_X) { ax = di * v.x; ay = di * v.y; az = di * v.z; aw = di * v.w; }
    else        { ax = v.x;      ay = v.y;      az = v.z;      aw = v.w; }
    int e  = g_off[i];
    int e1 = g_off[i + 1];
    for (; e + 4 <= e1; e += 4) {
        int s0 = g_col[e + 0], s1 = g_col[e + 1], s2 = g_col[e + 2], s3 = g_col[e + 3];
        float4 v0 = X4[(size_t)s0 * 32 + lane];
        float4 v1 = X4[(size_t)s1 * 32 + lane];
        float4 v2 = X4[(size_t)s2 * 32 + lane];
        float4 v3 = X4[(size_t)s3 * 32 + lane];
        if (FROM_X) {
            float w0 = g_dinv[s0], w1 = g_dinv[s1], w2 = g_dinv[s2], w3 = g_dinv[s3];
            ax += w0 * v0.x + w1 * v1.x + w2 * v2.x + w3 * v3.x;
            ay += w0 * v0.y + w1 * v1.y + w2 * v2.y + w3 * v3.y;
            az += w0 * v0.z + w1 * v1.z + w2 * v2.z + w3 * v3.z;
            aw += w0 * v0.w + w1 * v1.w + w2 * v2.w + w3 * v3.w;
        } else {
            ax += v0.x + v1.x + v2.x + v3.x;
            ay += v0.y + v1.y + v2.y + v3.y;
            az += v0.z + v1.z + v2.z + v3.z;
            aw += v0.w + v1.w + v2.w + v3.w;
        }
    }
    for (; e < e1; ++e) {
        int s = g_col[e];
        float4 vv = X4[(size_t)s * 32 + lane];
        if (FROM_X) {
            float w = g_dinv[s];
            ax += w * vv.x; ay += w * vv.y; az += w * vv.z; aw += w * vv.w;
        } else {
            ax += vv.x; ay += vv.y; az += vv.z; aw += vv.w;
        }
    }
    ax *= di; ay *= di; az *= di; aw *= di;
    __nv_bfloat16 hx = __float2bfloat16(ax), hy = __float2bfloat16(ay);
    __nv_bfloat16 hz = __float2bfloat16(az), hw = __float2bfloat16(aw);
    __nv_bfloat16 lx = __float2bfloat16(ax - __bfloat162float(hx));
    __nv_bfloat16 ly = __float2bfloat16(ay - __bfloat162float(hy));
    __nv_bfloat16 lz = __float2bfloat16(az - __bfloat162float(hz));
    __nv_bfloat16 lw = __float2bfloat16(aw - __bfloat162float(hw));
    uint2 hv, lv;
    hv.x = ((uint32_t)__bfloat16_as_ushort(hy) << 16) | __bfloat16_as_ushort(hx);
    hv.y = ((uint32_t)__bfloat16_as_ushort(hw) << 16) | __bfloat16_as_ushort(hz);
    lv.x = ((uint32_t)__bfloat16_as_ushort(ly) << 16) | __bfloat16_as_ushort(lx);
    lv.y = ((uint32_t)__bfloat16_as_ushort(lw) << 16) | __bfloat16_as_ushort(lz);
    ((uint2*)g_Ah)[(size_t)i * 32 + lane] = hv;
    ((uint2*)g_Al)[(size_t)i * 32 + lane] = lv;
}

// ---------------- HMMA bf16 3-term GEMM (verified R8/R10) ----------------
// OUT: 0 = f32 g_bufB PRE-SCALED by dinv[row] (feeds layer-2 prop),
//      1 = bf16 split g_Ah/g_Al, 2 = f32 outp.
template<int N, bool RELU, int OUT, int LAY>
__global__ void __launch_bounds__(256) mma_gemm(const float* __restrict__ bias,
                                                float* __restrict__ outp) {
    constexpr int NT = N / 8;
    __shared__ uint4 sAh[128 * 4], sAl[128 * 4];
    __shared__ uint4 sBh[N * 4],   sBl[N * 4];

    const uint4* Wh = (LAY == 1) ? g_W1h : (LAY == 2) ? g_W2h : g_W3h;
    const uint4* Wl = (LAY == 1) ? g_W1l : (LAY == 2) ? g_W2l : g_W3l;

    int tid = threadIdx.x;
    int wid = tid >> 5;
    int lid = tid & 31;
    int m0  = blockIdx.x * 128;

    float acc[NT][4];
    #pragma unroll
    for (int t = 0; t < NT; ++t)
        #pragma unroll
        for (int j = 0; j < 4; ++j) acc[t][j] = 0.f;

    uint32_t sAh_b = smem_u32(sAh), sAl_b = smem_u32(sAl);
    uint32_t sBh_b = smem_u32(sBh), sBl_b = smem_u32(sBl);

    uint32_t a_row  = lid & 15;
    uint32_t a_half = lid >> 4;
    uint32_t a_x    = (a_row >> 1) & 3;
    uint32_t a_base = (wid * 16 + a_row) * 64;
    uint32_t b_c    = (lid & 7) + ((lid >> 4) & 1) * 8;
    uint32_t b_half = (lid >> 3) & 1;
    uint32_t b_x    = (b_c >> 1) & 3;
    uint32_t b_base = b_c * 64;

    for (int c = 0; c < 4; ++c) {
        #pragma unroll
        for (int f = tid; f < 128 * 4; f += 256) {
            int row = f >> 2, ch = f & 3;
            int gr = m0 + row;
            uint4 vh = make_uint4(0, 0, 0, 0), vl = vh;
            if (gr < NN) {
                size_t gi = (size_t)gr * 16 + c * 4 + ch;
                vh = g_Ah[gi]; vl = g_Al[gi];
            }
            int du = row * 4 + (ch ^ ((row >> 1) & 3));
            sAh[du] = vh; sAl[du] = vl;
        }
        #pragma unroll
        for (int f = tid; f < N * 4; f += 256) {
            int row = f >> 2, ch = f & 3;
            size_t gi = (size_t)row * 16 + c * 4 + ch;
            int du = row * 4 + (ch ^ ((row >> 1) & 3));
            sBh[du] = Wh[gi]; sBl[du] = Wl[gi];
        }
        __syncthreads();

        #pragma unroll
        for (int ks = 0; ks < 2; ++ks) {
            uint32_t aoff = a_base + (((ks * 2 + a_half) ^ a_x) << 4);
            uint32_t ah0, ah1, ah2, ah3, al0, al1, al2, al3;
            ldsm_x4(ah0, ah1, ah2, ah3, sAh_b + aoff);
            ldsm_x4(al0, al1, al2, al3, sAl_b + aoff);
            #pragma unroll
            for (int jp = 0; jp < NT / 2; ++jp) {
                uint32_t boff = jp * 1024 + b_base + (((ks * 2 + b_half) ^ b_x) << 4);
                uint32_t bh0, bh1, bh2, bh3, bl0, bl1, bl2, bl3;
                ldsm_x4(bh0, bh1, bh2, bh3, sBh_b + boff);
                mma_bf16(acc[2 * jp],     ah0, ah1, ah2, ah3, bh0, bh1);
                mma_bf16(acc[2 * jp + 1], ah0, ah1, ah2, ah3, bh2, bh3);
                mma_bf16(acc[2 * jp],     al0, al1, al2, al3, bh0, bh1);
                mma_bf16(acc[2 * jp + 1], al0, al1, al2, al3, bh2, bh3);
                ldsm_x4(bl0, bl1, bl2, bl3, sBl_b + boff);
                mma_bf16(acc[2 * jp],     ah0, ah1, ah2, ah3, bl0, bl1);
                mma_bf16(acc[2 * jp + 1], ah0, ah1, ah2, ah3, bl2, bl3);
            }
        }
        __syncthreads();
    }

    int g = lid >> 2, q = lid & 3;
    int r0 = m0 + wid * 16 + g;
    int r1 = r0 + 8;
    float sd0 = 1.f, sd1 = 1.f;
    if (OUT == 0) {
        sd0 = (r0 < NN) ? g_dinv[r0] : 0.f;
        sd1 = (r1 < NN) ? g_dinv[r1] : 0.f;
    }
    #pragma unroll
    for (int nt = 0; nt < NT; ++nt) {
        int col = nt * 8 + 2 * q;
        float2 bb = *(const float2*)&bias[col];
        float v0 = acc[nt][0] + bb.x, v1 = acc[nt][1] + bb.y;
        float v2 = acc[nt][2] + bb.x, v3 = acc[nt][3] + bb.y;
        if (RELU) {
            v0 = fmaxf(v0, 0.f); v1 = fmaxf(v1, 0.f);
            v2 = fmaxf(v2, 0.f); v3 = fmaxf(v3, 0.f);
        }
        if (OUT == 1) {
            __nv_bfloat16 h0 = __float2bfloat16(v0), h1 = __float2bfloat16(v1);
            __nv_bfloat16 h2 = __float2bfloat16(v2), h3 = __float2bfloat16(v3);
            ushort2 hp0, hp1, lp0, lp1;
            hp0.x = __bfloat16_as_ushort(h0); hp0.y = __bfloat16_as_ushort(h1);
            hp1.x = __bfloat16_as_ushort(h2); hp1.y = __bfloat16_as_ushort(h3);
            lp0.x = __bfloat16_as_ushort(__float2bfloat16(v0 - __bfloat162float(h0)));
            lp0.y = __bfloat16_as_ushort(__float2bfloat16(v1 - __bfloat162float(h1)));
            lp1.x = __bfloat16_as_ushort(__float2bfloat16(v2 - __bfloat162float(h2)));
            lp1.y = __bfloat16_as_ushort(__float2bfloat16(v3 - __bfloat162float(h3)));
            if (r0 < NN) {
                *(ushort2*)((__nv_bfloat16*)g_Ah + (size_t)r0 * 128 + col) = hp0;
                *(ushort2*)((__nv_bfloat16*)g_Al + (size_t)r0 * 128 + col) = lp0;
            }
            if (r1 < NN) {
                *(ushort2*)((__nv_bfloat16*)g_Ah + (size_t)r1 * 128 + col) = hp1;
                *(ushort2*)((__nv_bfloat16*)g_Al + (size_t)r1 * 128 + col) = lp1;
            }
        } else {
            float* C = (OUT == 2) ? outp : (float*)g_bufB;
            if (r0 < NN) *(float2*)&C[(size_t)r0 * N + col] = make_float2(v0 * sd0, v1 * sd0);
            if (r1 < NN) *(float2*)&C[(size_t)r1 * N + col] = make_float2(v2 * sd1, v3 * sd1);
        }
    }
}

// ---------------- launch ----------------
extern "C" void kernel_launch(void* const* d_in, const int* in_sizes, int n_in,
                              void* d_out, int out_size) {
    const float* x  = (const float*)d_in[0];
    const float* W1 = (const float*)d_in[2];
    const float* b1 = (const float*)d_in[3];
    const float* W2 = (const float*)d_in[4];
    const float* b2 = (const float*)d_in[5];
    const float* Wl = (const float*)d_in[6];
    const float* bl = (const float*)d_in[7];
    float*       out = (float*)d_out;

    // CSR build + weight split
    zero_cnt_kernel<<<NB, 256>>>();
    edges_kernel<<<(NE + 255) / 256, 256>>>((const unsigned int*)d_in[1]);
    split_w_kernel<<<160, 256>>>(W1, W2, Wl);
    scan1_kernel<<<NB, 256>>>();
    scan2_kernel<<<1, 64>>>();
    scan3_kernel<<<NB, 256>>>();
    fill_kernel<<<(NE + 255) / 256, 256>>>();

    dim3 pgrid((NN + 7) / 8);
    dim3 ggrid((NN + 127) / 128);   // 391 CTAs

    // layer 1: propagate(x) -> Ah/Al ; GEMM -> bufB (f32, relu, PRE-SCALED by dinv)
    prop_kernel<true><<<pgrid, 256>>>(x);
    mma_gemm<128, true, 0, 1><<<ggrid, 256>>>(b1, nullptr);
    // layer 2: propagate(bufB scaled) -> Ah/Al ; GEMM -> Ah/Al (bf16 split, relu)
    prop_kernel<false><<<pgrid, 256>>>(nullptr);
    mma_gemm<128, true, 1, 2><<<ggrid, 256>>>(b2, nullptr);
    // head: Ah/Al @ Wl + bl -> out
    mma_gemm<64, false, 2, 3><<<ggrid, 256>>>(bl, out);
}

// round 17
// speedup vs baseline: 1.4606x; 1.0086x over previous
#include <cuda_runtime.h>
#include <cuda_bf16.h>
#include <cstdint>

#define NN 50000
#define NE 640000
#define DD 128
#define NCLS 64
#define NB 49          // scan blocks: 49*1024 = 50176 >= NN

// ---------------- scratch (device globals) ----------------
__device__ uint4  g_Ah[(size_t)NN * 16];   // [NN][128] bf16 hi
__device__ uint4  g_Al[(size_t)NN * 16];   // [NN][128] bf16 lo
__device__ float4 g_bufB[(size_t)NN * 32]; // [NN][128] f32 (h1 pre-scaled by dinv)
__device__ uint4  g_W1h[128 * 16], g_W1l[128 * 16];  // W^T [n][k] bf16
__device__ uint4  g_W2h[128 * 16], g_W2l[128 * 16];
__device__ uint4  g_W3h[64 * 16],  g_W3l[64 * 16];
__device__ int4   g_cnt4[NB * 256];        // 50176 counters (16B-aligned)
__device__ int    g_bsum[NB];
__device__ int    g_off[NN + 1];
__device__ float  g_dinv[NN];
__device__ int    g_col[NE];
__device__ int    g_src[NE];
__device__ int    g_dst[NE];
__device__ int    g_rank[NE];

// ---------------- helpers ----------------
__device__ __forceinline__ uint32_t smem_u32(const void* p) {
    uint32_t a;
    asm("{ .reg .u64 t; cvta.to.shared.u64 t, %1; cvt.u32.u64 %0, t; }" : "=r"(a) : "l"(p));
    return a;
}
__device__ __forceinline__ void ldsm_x4(uint32_t& r0, uint32_t& r1, uint32_t& r2, uint32_t& r3,
                                        uint32_t addr) {
    asm volatile("ldmatrix.sync.aligned.m8n8.x4.shared.b16 {%0,%1,%2,%3}, [%4];"
                 : "=r"(r0), "=r"(r1), "=r"(r2), "=r"(r3) : "r"(addr));
}
__device__ __forceinline__ void mma_bf16(float* c, uint32_t a0, uint32_t a1, uint32_t a2,
                                         uint32_t a3, uint32_t b0, uint32_t b1) {
    asm volatile(
        "mma.sync.aligned.m16n8k16.row.col.f32.bf16.bf16.f32 "
        "{%0,%1,%2,%3}, {%4,%5,%6,%7}, {%8,%9}, {%0,%1,%2,%3};"
        : "+f"(c[0]), "+f"(c[1]), "+f"(c[2]), "+f"(c[3])
        : "r"(a0), "r"(a1), "r"(a2), "r"(a3), "r"(b0), "r"(b1));
}
__device__ __forceinline__ int warp_iscan(int v, int lane) {
    #pragma unroll
    for (int d = 1; d < 32; d <<= 1) {
        int t = __shfl_up_sync(0xffffffffu, v, d);
        if (lane >= d) v += t;
    }
    return v;
}

// ---------------- CSR build ----------------
__global__ void zero_cnt_kernel() {
    int i = blockIdx.x * blockDim.x + threadIdx.x;
    if (i < NB * 256) g_cnt4[i] = make_int4(0, 0, 0, 0);
}

// fused dtype-detect + normalize + histogram; atomic RETURN is the per-dst rank
__global__ void edges_kernel(const unsigned int* __restrict__ raw) {
    __shared__ int s_is64;
    if (threadIdx.x < 32) {
        size_t k = (size_t)threadIdx.x * (NE / 32);
        unsigned int hi = raw[2 * k + 1];
        unsigned int any = __ballot_sync(0xffffffffu, hi != 0u);
        if (threadIdx.x == 0) s_is64 = (any == 0u);
    }
    __syncthreads();
    int is64 = s_is64;
    int e = blockIdx.x * blockDim.x + threadIdx.x;
    if (e >= NE) return;
    const int* raw32 = (const int*)raw;
    int s, d;
    if (is64) { s = raw32[2 * (size_t)e]; d = raw32[2 * ((size_t)NE + e)]; }
    else      { s = raw32[e];             d = raw32[NE + e]; }
    s = min(max(s, 0), NN - 1);
    d = min(max(d, 0), NN - 1);
    g_src[e] = s;
    g_dst[e] = d;
    g_rank[e] = atomicAdd(&((int*)g_cnt4)[d], 1);
}

// ---- scan phase 1: per-block totals ----
__global__ void scan1_kernel() {
    __shared__ int wsum[8];
    int t = threadIdx.x, b = blockIdx.x;
    int lane = t & 31, w = t >> 5;
    int4 v = g_cnt4[b * 256 + t];
    int s = v.x + v.y + v.z + v.w;
    int inc = warp_iscan(s, lane);
    if (lane == 31) wsum[w] = inc;
    __syncthreads();
    if (t == 0) {
        int tot = 0;
        #pragma unroll
        for (int i = 0; i < 8; ++i) tot += wsum[i];
        g_bsum[b] = tot;
    }
}

// ---- scan phase 2 (fused, race-free): each block scans the 49 partials itself,
// then rescans its own chunk; emits off + dinv. off[NN] == NE (constant).
// bpre ownership: warp 0 writes [0..31], warp 1 writes [32..NB); nobody else.
__global__ void scan3_kernel() {
    __shared__ int wsum[8];
    __shared__ int bpre[64];
    int t = threadIdx.x, b = blockIdx.x;
    int lane = t & 31, w = t >> 5;
    if (w == 0) {
        int s = (lane < NB) ? g_bsum[lane] : 0;
        int inc = warp_iscan(s, lane);
        bpre[lane] = inc - s;                       // exclusive prefix of partials 0..31
    } else if (w == 1) {
        int idx = 32 + lane;
        int s = (idx < NB) ? g_bsum[idx] : 0;
        int inc = warp_iscan(s, lane);
        if (idx < NB) bpre[idx] = inc - s;          // + sum(first 32) added below
    }
    __syncthreads();
    if (t == 0) {
        int t32 = 0;
        #pragma unroll
        for (int i = 0; i < 32; ++i) t32 += g_bsum[i];
        for (int i = 32; i < NB; ++i) bpre[i] += t32;
    }
    __syncthreads();
    int4 v = g_cnt4[b * 256 + t];
    int s = v.x + v.y + v.z + v.w;
    int inc = warp_iscan(s, lane);
    if (lane == 31) wsum[w] = inc;
    __syncthreads();
    int woff = 0;
    #pragma unroll
    for (int i = 0; i < 8; ++i) if (i < w) woff += wsum[i];
    int excl = bpre[b] + woff + inc - s;
    int i0 = (b * 256 + t) * 4;
    int e0 = excl, e1 = e0 + v.x, e2 = e1 + v.y, e3 = e2 + v.z;
    if (i0 + 0 < NN) { g_off[i0 + 0] = e0; g_dinv[i0 + 0] = rsqrtf((float)(v.x + 1)); }
    if (i0 + 1 < NN) { g_off[i0 + 1] = e1; g_dinv[i0 + 1] = rsqrtf((float)(v.y + 1)); }
    if (i0 + 2 < NN) { g_off[i0 + 2] = e2; g_dinv[i0 + 2] = rsqrtf((float)(v.z + 1)); }
    if (i0 + 3 < NN) { g_off[i0 + 3] = e3; g_dinv[i0 + 3] = rsqrtf((float)(v.w + 1)); }
    if (b == 0 && t == 0) g_off[NN] = NE;           // every clamped edge counted
}

// atomic-free fill: position = off[dst] + rank  (pure scatter)
__global__ void fill_kernel() {
    int e = blockIdx.x * blockDim.x + threadIdx.x;
    if (e < NE) {
        g_col[g_off[g_dst[e]] + g_rank[e]] = g_src[e];
    }
}

// ---------------- weight split ----------------
__global__ void split_w_kernel(const float* __restrict__ W1, const float* __restrict__ W2,
                               const float* __restrict__ W3) {
    int i = blockIdx.x * blockDim.x + threadIdx.x;
    float v; __nv_bfloat16* dh; __nv_bfloat16* dl; int n, k;
    if (i < 16384) {
        v = W1[i]; k = i >> 7; n = i & 127;
        dh = (__nv_bfloat16*)g_W1h; dl = (__nv_bfloat16*)g_W1l;
    } else if (i < 32768) {
        int j = i - 16384;
        v = W2[j]; k = j >> 7; n = j & 127;
        dh = (__nv_bfloat16*)g_W2h; dl = (__nv_bfloat16*)g_W2l;
    } else if (i < 40960) {
        int j = i - 32768;
        v = W3[j]; k = j >> 6; n = j & 63;
        dh = (__nv_bfloat16*)g_W3h; dl = (__nv_bfloat16*)g_W3l;
    } else return;
    __nv_bfloat16 h = __float2bfloat16(v);
    __nv_bfloat16 l = __float2bfloat16(v - __bfloat162float(h));
    dh[n * 128 + k] = h;
    dl[n * 128 + k] = l;
}

// ---------------- sparse propagate -> bf16 hi/lo split (verified R15) ----------------
template<bool FROM_X>
__global__ void prop_kernel(const float* __restrict__ xin) {
    int warp = (blockIdx.x * blockDim.x + threadIdx.x) >> 5;
    int lane = threadIdx.x & 31;
    if (warp >= NN) return;
    const float4* X4 = FROM_X ? (const float4*)xin : (const float4*)g_bufB;
    int i = warp;
    float di = g_dinv[i];
    float4 v = X4[(size_t)i * 32 + lane];
    float ax, ay, az, aw;
    if (FROM_X) { ax = di * v.x; ay = di * v.y; az = di * v.z; aw = di * v.w; }
    else        { ax = v.x;      ay = v.y;      az = v.z;      aw = v.w; }
    int e  = g_off[i];
    int e1 = g_off[i + 1];
    for (; e + 4 <= e1; e += 4) {
        int s0 = g_col[e + 0], s1 = g_col[e + 1], s2 = g_col[e + 2], s3 = g_col[e + 3];
        float4 v0 = X4[(size_t)s0 * 32 + lane];
        float4 v1 = X4[(size_t)s1 * 32 + lane];
        float4 v2 = X4[(size_t)s2 * 32 + lane];
        float4 v3 = X4[(size_t)s3 * 32 + lane];
        if (FROM_X) {
            float w0 = g_dinv[s0], w1 = g_dinv[s1], w2 = g_dinv[s2], w3 = g_dinv[s3];
            ax += w0 * v0.x + w1 * v1.x + w2 * v2.x + w3 * v3.x;
            ay += w0 * v0.y + w1 * v1.y + w2 * v2.y + w3 * v3.y;
            az += w0 * v0.z + w1 * v1.z + w2 * v2.z + w3 * v3.z;
            aw += w0 * v0.w + w1 * v1.w + w2 * v2.w + w3 * v3.w;
        } else {
            ax += v0.x + v1.x + v2.x + v3.x;
            ay += v0.y + v1.y + v2.y + v3.y;
            az += v0.z + v1.z + v2.z + v3.z;
            aw += v0.w + v1.w + v2.w + v3.w;
        }
    }
    for (; e < e1; ++e) {
        int s = g_col[e];
        float4 vv = X4[(size_t)s * 32 + lane];
        if (FROM_X) {
            float w = g_dinv[s];
            ax += w * vv.x; ay += w * vv.y; az += w * vv.z; aw += w * vv.w;
        } else {
            ax += vv.x; ay += vv.y; az += vv.z; aw += vv.w;
        }
    }
    ax *= di; ay *= di; az *= di; aw *= di;
    __nv_bfloat16 hx = __float2bfloat16(ax), hy = __float2bfloat16(ay);
    __nv_bfloat16 hz = __float2bfloat16(az), hw = __float2bfloat16(aw);
    __nv_bfloat16 lx = __float2bfloat16(ax - __bfloat162float(hx));
    __nv_bfloat16 ly = __float2bfloat16(ay - __bfloat162float(hy));
    __nv_bfloat16 lz = __float2bfloat16(az - __bfloat162float(hz));
    __nv_bfloat16 lw = __float2bfloat16(aw - __bfloat162float(hw));
    uint2 hv, lv;
    hv.x = ((uint32_t)__bfloat16_as_ushort(hy) << 16) | __bfloat16_as_ushort(hx);
    hv.y = ((uint32_t)__bfloat16_as_ushort(hw) << 16) | __bfloat16_as_ushort(hz);
    lv.x = ((uint32_t)__bfloat16_as_ushort(ly) << 16) | __bfloat16_as_ushort(lx);
    lv.y = ((uint32_t)__bfloat16_as_ushort(lw) << 16) | __bfloat16_as_ushort(lz);
    ((uint2*)g_Ah)[(size_t)i * 32 + lane] = hv;
    ((uint2*)g_Al)[(size_t)i * 32 + lane] = lv;
}

// ---------------- HMMA bf16 3-term GEMM (verified R8/R10/R15) ----------------
// OUT: 0 = f32 g_bufB PRE-SCALED by dinv[row], 1 = bf16 split g_Ah/g_Al, 2 = f32 outp.
template<int N, bool RELU, int OUT, int LAY>
__global__ void __launch_bounds__(256) mma_gemm(const float* __restrict__ bias,
                                                float* __restrict__ outp) {
    constexpr int NT = N / 8;
    __shared__ uint4 sAh[128 * 4], sAl[128 * 4];
    __shared__ uint4 sBh[N * 4],   sBl[N * 4];

    const uint4* Wh = (LAY == 1) ? g_W1h : (LAY == 2) ? g_W2h : g_W3h;
    const uint4* Wl = (LAY == 1) ? g_W1l : (LAY == 2) ? g_W2l : g_W3l;

    int tid = threadIdx.x;
    int wid = tid >> 5;
    int lid = tid & 31;
    int m0  = blockIdx.x * 128;

    float acc[NT][4];
    #pragma unroll
    for (int t = 0; t < NT; ++t)
        #pragma unroll
        for (int j = 0; j < 4; ++j) acc[t][j] = 0.f;

    uint32_t sAh_b = smem_u32(sAh), sAl_b = smem_u32(sAl);
    uint32_t sBh_b = smem_u32(sBh), sBl_b = smem_u32(sBl);

    uint32_t a_row  = lid & 15;
    uint32_t a_half = lid >> 4;
    uint32_t a_x    = (a_row >> 1) & 3;
    uint32_t a_base = (wid * 16 + a_row) * 64;
    uint32_t b_c    = (lid & 7) + ((lid >> 4) & 1) * 8;
    uint32_t b_half = (lid >> 3) & 1;
    uint32_t b_x    = (b_c >> 1) & 3;
    uint32_t b_base = b_c * 64;

    for (int c = 0; c < 4; ++c) {
        #pragma unroll
        for (int f = tid; f < 128 * 4; f += 256) {
            int row = f >> 2, ch = f & 3;
            int gr = m0 + row;
            uint4 vh = make_uint4(0, 0, 0, 0), vl = vh;
            if (gr < NN) {
                size_t gi = (size_t)gr * 16 + c * 4 + ch;
                vh = g_Ah[gi]; vl = g_Al[gi];
            }
            int du = row * 4 + (ch ^ ((row >> 1) & 3));
            sAh[du] = vh; sAl[du] = vl;
        }
        #pragma unroll
        for (int f = tid; f < N * 4; f += 256) {
            int row = f >> 2, ch = f & 3;
            size_t gi = (size_t)row * 16 + c * 4 + ch;
            int du = row * 4 + (ch ^ ((row >> 1) & 3));
            sBh[du] = Wh[gi]; sBl[du] = Wl[gi];
        }
        __syncthreads();

        #pragma unroll
        for (int ks = 0; ks < 2; ++ks) {
            uint32_t aoff = a_base + (((ks * 2 + a_half) ^ a_x) << 4);
            uint32_t ah0, ah1, ah2, ah3, al0, al1, al2, al3;
            ldsm_x4(ah0, ah1, ah2, ah3, sAh_b + aoff);
            ldsm_x4(al0, al1, al2, al3, sAl_b + aoff);
            #pragma unroll
            for (int jp = 0; jp < NT / 2; ++jp) {
                uint32_t boff = jp * 1024 + b_base + (((ks * 2 + b_half) ^ b_x) << 4);
                uint32_t bh0, bh1, bh2, bh3, bl0, bl1, bl2, bl3;
                ldsm_x4(bh0, bh1, bh2, bh3, sBh_b + boff);
                mma_bf16(acc[2 * jp],     ah0, ah1, ah2, ah3, bh0, bh1);
                mma_bf16(acc[2 * jp + 1], ah0, ah1, ah2, ah3, bh2, bh3);
                mma_bf16(acc[2 * jp],     al0, al1, al2, al3, bh0, bh1);
                mma_bf16(acc[2 * jp + 1], al0, al1, al2, al3, bh2, bh3);
                ldsm_x4(bl0, bl1, bl2, bl3, sBl_b + boff);
                mma_bf16(acc[2 * jp],     ah0, ah1, ah2, ah3, bl0, bl1);
                mma_bf16(acc[2 * jp + 1], ah0, ah1, ah2, ah3, bl2, bl3);
            }
        }
        __syncthreads();
    }

    int g = lid >> 2, q = lid & 3;
    int r0 = m0 + wid * 16 + g;
    int r1 = r0 + 8;
    float sd0 = 1.f, sd1 = 1.f;
    if (OUT == 0) {
        sd0 = (r0 < NN) ? g_dinv[r0] : 0.f;
        sd1 = (r1 < NN) ? g_dinv[r1] : 0.f;
    }
    #pragma unroll
    for (int nt = 0; nt < NT; ++nt) {
        int col = nt * 8 + 2 * q;
        float2 bb = *(const float2*)&bias[col];
        float v0 = acc[nt][0] + bb.x, v1 = acc[nt][1] + bb.y;
        float v2 = acc[nt][2] + bb.x, v3 = acc[nt][3] + bb.y;
        if (RELU) {
            v0 = fmaxf(v0, 0.f); v1 = fmaxf(v1, 0.f);
            v2 = fmaxf(v2, 0.f); v3 = fmaxf(v3, 0.f);
        }
        if (OUT == 1) {
            __nv_bfloat16 h0 = __float2bfloat16(v0), h1 = __float2bfloat16(v1);
            __nv_bfloat16 h2 = __float2bfloat16(v2), h3 = __float2bfloat16(v3);
            ushort2 hp0, hp1, lp0, lp1;
            hp0.x = __bfloat16_as_ushort(h0); hp0.y = __bfloat16_as_ushort(h1);
            hp1.x = __bfloat16_as_ushort(h2); hp1.y = __bfloat16_as_ushort(h3);
            lp0.x = __bfloat16_as_ushort(__float2bfloat16(v0 - __bfloat162float(h0)));
            lp0.y = __bfloat16_as_ushort(__float2bfloat16(v1 - __bfloat162float(h1)));
            lp1.x = __bfloat16_as_ushort(__float2bfloat16(v2 - __bfloat162float(h2)));
            lp1.y = __bfloat16_as_ushort(__float2bfloat16(v3 - __bfloat162float(h3)));
            if (r0 < NN) {
                *(ushort2*)((__nv_bfloat16*)g_Ah + (size_t)r0 * 128 + col) = hp0;
                *(ushort2*)((__nv_bfloat16*)g_Al + (size_t)r0 * 128 + col) = lp0;
            }
            if (r1 < NN) {
                *(ushort2*)((__nv_bfloat16*)g_Ah + (size_t)r1 * 128 + col) = hp1;
                *(ushort2*)((__nv_bfloat16*)g_Al + (size_t)r1 * 128 + col) = lp1;
            }
        } else {
            float* C = (OUT == 2) ? outp : (float*)g_bufB;
            if (r0 < NN) *(float2*)&C[(size_t)r0 * N + col] = make_float2(v0 * sd0, v1 * sd0);
            if (r1 < NN) *(float2*)&C[(size_t)r1 * N + col] = make_float2(v2 * sd1, v3 * sd1);
        }
    }
}

// ---------------- launch ----------------
extern "C" void kernel_launch(void* const* d_in, const int* in_sizes, int n_in,
                              void* d_out, int out_size) {
    const float* x  = (const float*)d_in[0];
    const float* W1 = (const float*)d_in[2];
    const float* b1 = (const float*)d_in[3];
    const float* W2 = (const float*)d_in[4];
    const float* b2 = (const float*)d_in[5];
    const float* Wl = (const float*)d_in[6];
    const float* bl = (const float*)d_in[7];
    float*       out = (float*)d_out;

    // CSR build + weight split
    zero_cnt_kernel<<<NB, 256>>>();
    edges_kernel<<<(NE + 255) / 256, 256>>>((const unsigned int*)d_in[1]);
    split_w_kernel<<<160, 256>>>(W1, W2, Wl);
    scan1_kernel<<<NB, 256>>>();
    scan3_kernel<<<NB, 256>>>();
    fill_kernel<<<(NE + 255) / 256, 256>>>();

    dim3 pgrid((NN + 7) / 8);
    dim3 ggrid((NN + 127) / 128);   // 391 CTAs

    // layer 1: propagate(x) -> Ah/Al ; GEMM -> bufB (f32, relu, PRE-SCALED by dinv)
    prop_kernel<true><<<pgrid, 256>>>(x);
    mma_gemm<128, true, 0, 1><<<ggrid, 256>>>(b1, nullptr);
    // layer 2: propagate(bufB scaled) -> Ah/Al ; GEMM -> Ah/Al (bf16 split, relu)
    prop_kernel<false><<<pgrid, 256>>>(nullptr);
    mma_gemm<128, true, 1, 2><<<ggrid, 256>>>(b2, nullptr);
    // head: Ah/Al @ Wl + bl -> out
    mma_gemm<64, false, 2, 3><<<ggrid, 256>>>(bl, out);
}